// round 1
// baseline (speedup 1.0000x reference)
#include <cuda_runtime.h>
#include <cstdint>

// Problem dims (fixed by the dataset)
#define Td  4
#define Bd  32
#define Cd  512
#define CVd 2048
#define Nd  256
#define NHd 8
#define DHd 64     // Cd / NHd
#define DVd 256    // CVd / NHd

// ---------------- scratch (static device globals; no allocs in kernel_launch) ----
__device__ float g_xs[(size_t)Td * Bd * Cd  * Nd];   //  67 MB
__device__ float g_q [(size_t)Td * Bd * Cd  * Nd];   //  67 MB
__device__ float g_k [(size_t)Td * Bd * Cd  * Nd];   //  67 MB
__device__ float g_v [(size_t)Td * Bd * CVd * Nd];   // 268 MB
__device__ float g_kv[(size_t)Td * Bd * NHd * DHd * DVd]; // 67 MB
__device__ float g_o [(size_t)Td * Bd * CVd * Nd];   // 268 MB

// ---------------- SFA: sequential scan over T, parallel over (b,c,n) ------------
// u = h + x_t ; s = round_half_even(clip(u,0,8)) ; h = u - s ; y_t = s/8
__global__ void sfa_kernel(const float* __restrict__ in, float* __restrict__ out, int perT)
{
    int i = blockIdx.x * blockDim.x + threadIdx.x;
    if (i >= perT) return;
    float h = 0.f;
#pragma unroll
    for (int t = 0; t < Td; ++t) {
        float u = h + in[(size_t)t * perT + i];
        float s = rintf(fminf(fmaxf(u, 0.f), 8.f));   // rintf == round-half-to-even
        h = u - s;
        out[(size_t)t * perT + i] = s * 0.125f;
    }
}

// ---------------- generic batched GEMM + BN affine ------------------------------
// Y[z][m][n] = scale[m] * (sum_k W[m][k] * X[z][k][n]) + bias[m]
// W row-major [M,K]; X batched [TB, K, Nd]; Y batched [TB, M, Nd]
// Block tile 64x64, K-step 16, 256 threads, 4x4 per-thread microtile.
__global__ void __launch_bounds__(256)
gemm_bn_kernel(const float* __restrict__ W, const float* __restrict__ Xall,
               float* __restrict__ Yall, const float* __restrict__ scale,
               const float* __restrict__ bias, int M, int K)
{
    __shared__ float As[16][64];   // [k][m]
    __shared__ float Bs[16][64];   // [k][n]

    const int tid = threadIdx.x;
    const int tx = tid & 15, ty = tid >> 4;
    const int mBase = blockIdx.y * 64;
    const int nBase = blockIdx.x * 64;

    const float* X = Xall + (size_t)blockIdx.z * K * Nd;
    float*       Y = Yall + (size_t)blockIdx.z * M * Nd;

    // A loader: row ar (64 rows), 4 contiguous k at akq -> transpose into As
    const int ar  = tid >> 2;
    const int akq = (tid & 3) * 4;
    // B loader: k-row bk (16 rows), 4 contiguous n at bnq -> direct into Bs
    const int bk  = tid >> 4;
    const int bnq = (tid & 15) * 4;

    const float* Aptr = W + (size_t)(mBase + ar) * K + akq;

    float acc[4][4];
#pragma unroll
    for (int i = 0; i < 4; ++i)
#pragma unroll
        for (int j = 0; j < 4; ++j) acc[i][j] = 0.f;

    for (int kb = 0; kb < K; kb += 16) {
        float4 av = *(const float4*)(Aptr + kb);
        float4 bv = *(const float4*)(X + (size_t)(kb + bk) * Nd + nBase + bnq);
        As[akq + 0][ar] = av.x; As[akq + 1][ar] = av.y;
        As[akq + 2][ar] = av.z; As[akq + 3][ar] = av.w;
        *(float4*)&Bs[bk][bnq] = bv;
        __syncthreads();
#pragma unroll
        for (int kk = 0; kk < 16; ++kk) {
            float4 a = *(const float4*)&As[kk][ty * 4];
            float4 b = *(const float4*)&Bs[kk][tx * 4];
            acc[0][0] += a.x * b.x; acc[0][1] += a.x * b.y; acc[0][2] += a.x * b.z; acc[0][3] += a.x * b.w;
            acc[1][0] += a.y * b.x; acc[1][1] += a.y * b.y; acc[1][2] += a.y * b.z; acc[1][3] += a.y * b.w;
            acc[2][0] += a.z * b.x; acc[2][1] += a.z * b.y; acc[2][2] += a.z * b.z; acc[2][3] += a.z * b.w;
            acc[3][0] += a.w * b.x; acc[3][1] += a.w * b.y; acc[3][2] += a.w * b.z; acc[3][3] += a.w * b.w;
        }
        __syncthreads();
    }

#pragma unroll
    for (int i = 0; i < 4; ++i) {
        int m = mBase + ty * 4 + i;
        float sc = scale[m], bi = bias[m];
        float4 o;
        o.x = acc[i][0] * sc + bi;
        o.y = acc[i][1] * sc + bi;
        o.z = acc[i][2] * sc + bi;
        o.w = acc[i][3] * sc + bi;
        *(float4*)(Y + (size_t)m * Nd + nBase + tx * 4) = o;
    }
}

// ---------------- attention phase 1: kv[d][e] = sum_n K[d,n] * V[e,n] -----------
// Per z = (t*B+b)*8+h.  A = K head-slice [64 x 256] (k contiguous),
// B = V head-slice [256 x 256] (k contiguous).  NT-GEMM, both transposed on load.
__global__ void __launch_bounds__(256)
kv_kernel()
{
    __shared__ float As[16][64];   // [k][d]
    __shared__ float Bs[16][64];   // [k][e]

    const int tid = threadIdx.x;
    const int tx = tid & 15, ty = tid >> 4;
    const int z  = blockIdx.z;            // t*B*NH + b*NH + h  (tb = z>>3, h = z&7)
    const int tb = z >> 3, h = z & 7;
    const int eBase = blockIdx.x * 64;

    const float* Ak = g_k + ((size_t)tb * Cd  + h * DHd) * Nd;
    const float* Bv = g_v + ((size_t)tb * CVd + h * DVd) * Nd;
    float*       KV = g_kv + (size_t)z * DHd * DVd;

    const int r  = tid >> 2;
    const int kq = (tid & 3) * 4;

    float acc[4][4];
#pragma unroll
    for (int i = 0; i < 4; ++i)
#pragma unroll
        for (int j = 0; j < 4; ++j) acc[i][j] = 0.f;

    for (int kb = 0; kb < Nd; kb += 16) {
        float4 av = *(const float4*)(Ak + (size_t)r * Nd + kb + kq);
        float4 bv = *(const float4*)(Bv + (size_t)(eBase + r) * Nd + kb + kq);
        As[kq + 0][r] = av.x; As[kq + 1][r] = av.y; As[kq + 2][r] = av.z; As[kq + 3][r] = av.w;
        Bs[kq + 0][r] = bv.x; Bs[kq + 1][r] = bv.y; Bs[kq + 2][r] = bv.z; Bs[kq + 3][r] = bv.w;
        __syncthreads();
#pragma unroll
        for (int kk = 0; kk < 16; ++kk) {
            float4 a = *(const float4*)&As[kk][ty * 4];
            float4 b = *(const float4*)&Bs[kk][tx * 4];
            acc[0][0] += a.x * b.x; acc[0][1] += a.x * b.y; acc[0][2] += a.x * b.z; acc[0][3] += a.x * b.w;
            acc[1][0] += a.y * b.x; acc[1][1] += a.y * b.y; acc[1][2] += a.y * b.z; acc[1][3] += a.y * b.w;
            acc[2][0] += a.z * b.x; acc[2][1] += a.z * b.y; acc[2][2] += a.z * b.z; acc[2][3] += a.z * b.w;
            acc[3][0] += a.w * b.x; acc[3][1] += a.w * b.y; acc[3][2] += a.w * b.z; acc[3][3] += a.w * b.w;
        }
        __syncthreads();
    }

#pragma unroll
    for (int i = 0; i < 4; ++i) {
        int d = ty * 4 + i;
        float4 o; o.x = acc[i][0]; o.y = acc[i][1]; o.z = acc[i][2]; o.w = acc[i][3];
        *(float4*)(KV + (size_t)d * DVd + eBase + tx * 4) = o;
    }
}

// ---------------- attention phase 2: O[e][n] = 0.25 * sum_d kv[d][e] * Q[d,n] ---
// A = kv [64 x 256] (e contiguous -> direct [k][m]); B = Q head-slice [64 x 256]
// (n contiguous -> direct [k][n]).  scale*2 = 64^-0.5 * 2 = 0.25 exactly.
__global__ void __launch_bounds__(256)
av_kernel()
{
    __shared__ float As[16][64];   // [d][e]
    __shared__ float Bs[16][64];   // [d][n]

    const int tid = threadIdx.x;
    const int tx = tid & 15, ty = tid >> 4;
    const int z  = blockIdx.z;
    const int tb = z >> 3, h = z & 7;
    const int eBase = blockIdx.y * 64;
    const int nBase = blockIdx.x * 64;

    const float* KV = g_kv + (size_t)z * DHd * DVd;
    const float* Q  = g_q + ((size_t)tb * Cd  + h * DHd) * Nd;
    float*       O  = g_o + ((size_t)tb * CVd + h * DVd) * Nd;

    const int bk = tid >> 4;
    const int bq = (tid & 15) * 4;

    float acc[4][4];
#pragma unroll
    for (int i = 0; i < 4; ++i)
#pragma unroll
        for (int j = 0; j < 4; ++j) acc[i][j] = 0.f;

    for (int kb = 0; kb < DHd; kb += 16) {
        *(float4*)&As[bk][bq] = *(const float4*)(KV + (size_t)(kb + bk) * DVd + eBase + bq);
        *(float4*)&Bs[bk][bq] = *(const float4*)(Q  + (size_t)(kb + bk) * Nd  + nBase + bq);
        __syncthreads();
#pragma unroll
        for (int kk = 0; kk < 16; ++kk) {
            float4 a = *(const float4*)&As[kk][ty * 4];
            float4 b = *(const float4*)&Bs[kk][tx * 4];
            acc[0][0] += a.x * b.x; acc[0][1] += a.x * b.y; acc[0][2] += a.x * b.z; acc[0][3] += a.x * b.w;
            acc[1][0] += a.y * b.x; acc[1][1] += a.y * b.y; acc[1][2] += a.y * b.z; acc[1][3] += a.y * b.w;
            acc[2][0] += a.z * b.x; acc[2][1] += a.z * b.y; acc[2][2] += a.z * b.z; acc[2][3] += a.z * b.w;
            acc[3][0] += a.w * b.x; acc[3][1] += a.w * b.y; acc[3][2] += a.w * b.z; acc[3][3] += a.w * b.w;
        }
        __syncthreads();
    }

#pragma unroll
    for (int i = 0; i < 4; ++i) {
        int e = eBase + ty * 4 + i;
        float4 o;
        o.x = acc[i][0] * 0.25f; o.y = acc[i][1] * 0.25f;
        o.z = acc[i][2] * 0.25f; o.w = acc[i][3] * 0.25f;
        *(float4*)(O + (size_t)e * Nd + nBase + tx * 4) = o;
    }
}

// ---------------- launch --------------------------------------------------------
extern "C" void kernel_launch(void* const* d_in, const int* in_sizes, int n_in,
                              void* d_out, int out_size)
{
    (void)in_sizes; (void)n_in; (void)out_size;

    const float* x       = (const float*)d_in[0];
    const float* wq      = (const float*)d_in[1];
    const float* wk      = (const float*)d_in[2];
    const float* wv      = (const float*)d_in[3];
    const float* wp      = (const float*)d_in[4];
    const float* q_scale = (const float*)d_in[5];
    const float* q_bias  = (const float*)d_in[6];
    const float* k_scale = (const float*)d_in[7];
    const float* k_bias  = (const float*)d_in[8];
    const float* v_scale = (const float*)d_in[9];
    const float* v_bias  = (const float*)d_in[10];
    const float* p_scale = (const float*)d_in[11];
    const float* p_bias  = (const float*)d_in[12];
    float* out = (float*)d_out;

    void* p;
    cudaGetSymbolAddress(&p, g_xs); float* xs = (float*)p;
    cudaGetSymbolAddress(&p, g_q ); float* q  = (float*)p;
    cudaGetSymbolAddress(&p, g_k ); float* k  = (float*)p;
    cudaGetSymbolAddress(&p, g_v ); float* v  = (float*)p;
    cudaGetSymbolAddress(&p, g_o ); float* o  = (float*)p;

    const int perT1 = Bd * Cd  * Nd;   //  4,194,304
    const int perTv = Bd * CVd * Nd;   // 16,777,216

    // 1. head spikes
    sfa_kernel<<<perT1 / 256, 256>>>(x, xs, perT1);

    // 2. q/k/v 1x1 conv + BN
    gemm_bn_kernel<<<dim3(4,  8, Td * Bd), 256>>>(wq, xs, q, q_scale, q_bias, Cd,  Cd);
    gemm_bn_kernel<<<dim3(4,  8, Td * Bd), 256>>>(wk, xs, k, k_scale, k_bias, Cd,  Cd);
    gemm_bn_kernel<<<dim3(4, 32, Td * Bd), 256>>>(wv, xs, v, v_scale, v_bias, CVd, Cd);

    // 3. spike q/k/v (in place)
    sfa_kernel<<<perT1 / 256, 256>>>(q, q, perT1);
    sfa_kernel<<<perT1 / 256, 256>>>(k, k, perT1);
    sfa_kernel<<<perTv / 256, 256>>>(v, v, perTv);

    // 4. linear attention, reassociated:  O = 0.25 * Q^T (K V^T)
    kv_kernel<<<dim3(4, 1, Td * Bd * NHd), 256>>>();
    av_kernel<<<dim3(4, 4, Td * Bd * NHd), 256>>>();

    // 5. attn spike (in place)
    sfa_kernel<<<perTv / 256, 256>>>(o, o, perTv);

    // 6. projection conv + BN -> output
    gemm_bn_kernel<<<dim3(4, 8, Td * Bd), 256>>>(wp, o, out, p_scale, p_bias, Cd, CVd);
}

// round 2
// speedup vs baseline: 3.1391x; 3.1391x over previous
#include <cuda_runtime.h>
#include <cuda_fp16.h>
#include <mma.h>
#include <cstdint>

using namespace nvcuda;

// Problem dims (fixed)
#define Td  4
#define Bd  32
#define Cd  512
#define CVd 2048
#define Nd  256
#define NHd 8
#define DHd 64
#define DVd 256
#define TBd (Td*Bd)      // 128
#define Zd  (TBd*NHd)    // 1024

// ---------------- static scratch ------------------------------------------------
__device__ __half g_xs [(size_t)TBd*Cd *Nd];   // x spikes (fp16, exact)
__device__ float  g_qf [(size_t)TBd*Cd *Nd];   // conv outputs (fp32, pre-sfa)
__device__ float  g_kf [(size_t)TBd*Cd *Nd];
__device__ float  g_vf [(size_t)TBd*CVd*Nd];
__device__ __half g_qh [(size_t)TBd*Cd *Nd];   // q/k/v spikes (fp16, exact)
__device__ __half g_kh [(size_t)TBd*Cd *Nd];
__device__ __half g_vh [(size_t)TBd*CVd*Nd];
__device__ float  g_kv [(size_t)Zd*DHd*DVd];   // K V^T (fp32, exact)
__device__ __half g_kvhi[(size_t)Zd*DHd*DVd];  // lossless hi/lo split
__device__ __half g_kvlo[(size_t)Zd*DHd*DVd];
__device__ float  g_of [(size_t)TBd*CVd*Nd];   // attention out (fp32, exact)
__device__ __half g_oh [(size_t)TBd*CVd*Nd];   // attn spikes (fp16, exact)
// folded weights (scale folded in), split hi/lo
__device__ __half g_wq_hi[Cd*Cd],  g_wq_lo[Cd*Cd];
__device__ __half g_wk_hi[Cd*Cd],  g_wk_lo[Cd*Cd];
__device__ __half g_wv_hi[CVd*Cd], g_wv_lo[CVd*Cd];
__device__ __half g_wp_hi[Cd*CVd], g_wp_lo[Cd*CVd];
// broadcast bias tables [M][128] for accumulator init
__device__ float g_b2d_q[Cd*128], g_b2d_k[Cd*128], g_b2d_v[CVd*128], g_b2d_p[Cd*128];

// ---------------- prep kernels --------------------------------------------------
__global__ void prep_w(const float* __restrict__ w, const float* __restrict__ scale,
                       __half* __restrict__ hi, __half* __restrict__ lo, int M, int K)
{
    int i = blockIdx.x * blockDim.x + threadIdx.x;
    if (i >= M * K) return;
    float v = w[i] * scale[i / K];
    __half h = __float2half_rn(v);
    hi[i] = h;
    lo[i] = __float2half_rn(v - __half2float(h));
}

__global__ void prep_b(const float* __restrict__ bias, float* __restrict__ b2d, int M)
{
    int i = blockIdx.x * blockDim.x + threadIdx.x;
    if (i >= M * 128) return;
    b2d[i] = bias[i >> 7];
}

// ---------------- SFA scan: fp32 in -> fp16 spikes out --------------------------
__global__ void sfa_f2h(const float* __restrict__ in, __half* __restrict__ out, int perT)
{
    int i = blockIdx.x * blockDim.x + threadIdx.x;
    if (i >= perT) return;
    float h = 0.f;
#pragma unroll
    for (int t = 0; t < Td; ++t) {
        float u = h + in[(size_t)t * perT + i];
        float s = rintf(fminf(fmaxf(u, 0.f), 8.f));   // round-half-to-even == jnp.round
        h = u - s;
        out[(size_t)t * perT + i] = __float2half_rn(s * 0.125f);  // exact in fp16
    }
}

// ---------------- conv GEMM (wmma, split-fp16 weights, bias init) ----------------
// Y[z][m][n] = (Whi+Wlo)[m][k] * B[z][k][n] + bias[m]
// Block tile 128x128, BK=32, 8 warps (4x2), warp tile 32x64.
__global__ void __launch_bounds__(256, 2)
conv_wmma(const __half* __restrict__ Ahi, const __half* __restrict__ Alo,
          const __half* __restrict__ Ball, const float* __restrict__ b2d,
          float* __restrict__ Yall, int M, int K)
{
    __shared__ __half sAh[128][40];
    __shared__ __half sAl[128][40];
    __shared__ __half sB [32][136];

    const int tid = threadIdx.x;
    const int warp = tid >> 5;
    const int wy = warp >> 1, wx = warp & 1;
    const int mBase = blockIdx.y * 128, nBase = blockIdx.x * 128;

    const __half* B = Ball + (size_t)blockIdx.z * K * Nd;
    float*       Y = Yall + (size_t)blockIdx.z * M * Nd;

    wmma::fragment<wmma::accumulator, 16, 16, 16, float> acc[2][4];
#pragma unroll
    for (int i = 0; i < 2; ++i)
#pragma unroll
        for (int j = 0; j < 4; ++j)
            wmma::load_matrix_sync(acc[i][j],
                b2d + (size_t)(mBase + wy * 32 + i * 16) * 128 + wx * 64 + j * 16,
                128, wmma::mem_row_major);

    const int ar = tid >> 2, ac = (tid & 3) * 8;
    const int br = tid >> 4, bc = (tid & 15) * 8;

    for (int kb = 0; kb < K; kb += 32) {
        *(uint4*)&sAh[ar     ][ac] = *(const uint4*)&Ahi[(size_t)(mBase + ar     ) * K + kb + ac];
        *(uint4*)&sAh[ar + 64][ac] = *(const uint4*)&Ahi[(size_t)(mBase + ar + 64) * K + kb + ac];
        *(uint4*)&sAl[ar     ][ac] = *(const uint4*)&Alo[(size_t)(mBase + ar     ) * K + kb + ac];
        *(uint4*)&sAl[ar + 64][ac] = *(const uint4*)&Alo[(size_t)(mBase + ar + 64) * K + kb + ac];
        *(uint4*)&sB [br     ][bc] = *(const uint4*)&B[(size_t)(kb + br     ) * Nd + nBase + bc];
        *(uint4*)&sB [br + 16][bc] = *(const uint4*)&B[(size_t)(kb + br + 16) * Nd + nBase + bc];
        __syncthreads();
#pragma unroll
        for (int kk = 0; kk < 32; kk += 16) {
            wmma::fragment<wmma::matrix_a, 16, 16, 16, half, wmma::row_major> ah[2], al[2];
#pragma unroll
            for (int i = 0; i < 2; ++i) {
                wmma::load_matrix_sync(ah[i], &sAh[wy * 32 + i * 16][kk], 40);
                wmma::load_matrix_sync(al[i], &sAl[wy * 32 + i * 16][kk], 40);
            }
#pragma unroll
            for (int j = 0; j < 4; ++j) {
                wmma::fragment<wmma::matrix_b, 16, 16, 16, half, wmma::row_major> bf;
                wmma::load_matrix_sync(bf, &sB[kk][wx * 64 + j * 16], 136);
#pragma unroll
                for (int i = 0; i < 2; ++i) {
                    wmma::mma_sync(acc[i][j], ah[i], bf, acc[i][j]);
                    wmma::mma_sync(acc[i][j], al[i], bf, acc[i][j]);
                }
            }
        }
        __syncthreads();
    }

#pragma unroll
    for (int i = 0; i < 2; ++i)
#pragma unroll
        for (int j = 0; j < 4; ++j)
            wmma::store_matrix_sync(
                Y + (size_t)(mBase + wy * 32 + i * 16) * Nd + nBase + wx * 64 + j * 16,
                acc[i][j], Nd, wmma::mem_row_major);
}

// ---------------- attention phase 1: kv[d][e] = sum_n K[d,n] V[e,n] -------------
// One block per z. 8 warps (4x2), warp tile 16x128. Direct-from-global wmma loads.
__global__ void __launch_bounds__(256)
kv_wmma()
{
    const int tid = threadIdx.x, warp = tid >> 5;
    const int wy = warp >> 1, wx = warp & 1;
    const int z = blockIdx.x;
    const int tb = z >> 3, h = z & 7;

    const __half* Kp = g_kh + ((size_t)tb * Cd  + h * DHd) * Nd;
    const __half* Vp = g_vh + ((size_t)tb * CVd + h * DVd) * Nd;
    float*        KV = g_kv + (size_t)z * DHd * DVd;

    wmma::fragment<wmma::accumulator, 16, 16, 16, float> acc[8];
#pragma unroll
    for (int j = 0; j < 8; ++j) wmma::fill_fragment(acc[j], 0.f);

    for (int k0 = 0; k0 < Nd; k0 += 16) {
        wmma::fragment<wmma::matrix_a, 16, 16, 16, half, wmma::row_major> a;
        wmma::load_matrix_sync(a, Kp + (size_t)(wy * 16) * Nd + k0, Nd);
#pragma unroll
        for (int j = 0; j < 8; ++j) {
            wmma::fragment<wmma::matrix_b, 16, 16, 16, half, wmma::col_major> b;
            wmma::load_matrix_sync(b, Vp + (size_t)(wx * 128 + j * 16) * Nd + k0, Nd);
            wmma::mma_sync(acc[j], a, b, acc[j]);
        }
    }
#pragma unroll
    for (int j = 0; j < 8; ++j)
        wmma::store_matrix_sync(KV + (size_t)(wy * 16) * DVd + wx * 128 + j * 16,
                                acc[j], DVd, wmma::mem_row_major);
}

// ---------------- kv lossless hi/lo split ---------------------------------------
__global__ void kv_split(int n)
{
    int i = blockIdx.x * blockDim.x + threadIdx.x;
    if (i >= n) return;
    float v = g_kv[i];
    __half h = __float2half_rn(v);
    g_kvhi[i] = h;
    g_kvlo[i] = __float2half_rn(v - __half2float(h));  // exact (<=11 residual bits)
}

// ---------------- attention phase 2: O[e][n] = 0.25 * sum_d kv[d][e] Q[d,n] -----
// Block tile 128x128, K=64. A = kv (col_major view, hi+lo), B = Q (row_major).
__global__ void __launch_bounds__(256, 2)
av_wmma()
{
    const int tid = threadIdx.x, warp = tid >> 5;
    const int wy = warp >> 1, wx = warp & 1;
    const int z = blockIdx.z;
    const int tb = z >> 3, h = z & 7;
    const int eBase = blockIdx.y * 128, nBase = blockIdx.x * 128;

    const __half* KVh = g_kvhi + (size_t)z * DHd * DVd;
    const __half* KVl = g_kvlo + (size_t)z * DHd * DVd;
    const __half* Qp  = g_qh + ((size_t)tb * Cd  + h * DHd) * Nd;
    float*        O   = g_of + ((size_t)tb * CVd + h * DVd) * Nd;

    wmma::fragment<wmma::accumulator, 16, 16, 16, float> acc[2][4];
#pragma unroll
    for (int i = 0; i < 2; ++i)
#pragma unroll
        for (int j = 0; j < 4; ++j) wmma::fill_fragment(acc[i][j], 0.f);

    for (int k0 = 0; k0 < DHd; k0 += 16) {
        wmma::fragment<wmma::matrix_a, 16, 16, 16, half, wmma::col_major> ah[2], al[2];
#pragma unroll
        for (int i = 0; i < 2; ++i) {
            wmma::load_matrix_sync(ah[i], KVh + (eBase + wy * 32 + i * 16) + (size_t)k0 * DVd, DVd);
            wmma::load_matrix_sync(al[i], KVl + (eBase + wy * 32 + i * 16) + (size_t)k0 * DVd, DVd);
        }
#pragma unroll
        for (int j = 0; j < 4; ++j) {
            wmma::fragment<wmma::matrix_b, 16, 16, 16, half, wmma::row_major> b;
            wmma::load_matrix_sync(b, Qp + (size_t)k0 * Nd + nBase + wx * 64 + j * 16, Nd);
#pragma unroll
            for (int i = 0; i < 2; ++i) {
                wmma::mma_sync(acc[i][j], ah[i], b, acc[i][j]);
                wmma::mma_sync(acc[i][j], al[i], b, acc[i][j]);
            }
        }
    }
#pragma unroll
    for (int i = 0; i < 2; ++i)
#pragma unroll
        for (int j = 0; j < 4; ++j) {
#pragma unroll
            for (int e = 0; e < acc[i][j].num_elements; ++e) acc[i][j].x[e] *= 0.25f;
            wmma::store_matrix_sync(
                O + (size_t)(eBase + wy * 32 + i * 16) * Nd + nBase + wx * 64 + j * 16,
                acc[i][j], Nd, wmma::mem_row_major);
        }
}

// ---------------- launch --------------------------------------------------------
extern "C" void kernel_launch(void* const* d_in, const int* in_sizes, int n_in,
                              void* d_out, int out_size)
{
    (void)in_sizes; (void)n_in; (void)out_size;

    const float* x       = (const float*)d_in[0];
    const float* wq      = (const float*)d_in[1];
    const float* wk      = (const float*)d_in[2];
    const float* wv      = (const float*)d_in[3];
    const float* wp      = (const float*)d_in[4];
    const float* q_scale = (const float*)d_in[5];
    const float* q_bias  = (const float*)d_in[6];
    const float* k_scale = (const float*)d_in[7];
    const float* k_bias  = (const float*)d_in[8];
    const float* v_scale = (const float*)d_in[9];
    const float* v_bias  = (const float*)d_in[10];
    const float* p_scale = (const float*)d_in[11];
    const float* p_bias  = (const float*)d_in[12];
    float* out = (float*)d_out;

    void* p;
    cudaGetSymbolAddress(&p, g_xs);    __half* xs   = (__half*)p;
    cudaGetSymbolAddress(&p, g_qf);    float*  qf   = (float*)p;
    cudaGetSymbolAddress(&p, g_kf);    float*  kf   = (float*)p;
    cudaGetSymbolAddress(&p, g_vf);    float*  vf   = (float*)p;
    cudaGetSymbolAddress(&p, g_qh);    __half* qh   = (__half*)p;
    cudaGetSymbolAddress(&p, g_kh);    __half* kh   = (__half*)p;
    cudaGetSymbolAddress(&p, g_vh);    __half* vh   = (__half*)p;
    cudaGetSymbolAddress(&p, g_of);    float*  of   = (float*)p;
    cudaGetSymbolAddress(&p, g_oh);    __half* oh   = (__half*)p;
    cudaGetSymbolAddress(&p, g_wq_hi); __half* wqh  = (__half*)p;
    cudaGetSymbolAddress(&p, g_wq_lo); __half* wql  = (__half*)p;
    cudaGetSymbolAddress(&p, g_wk_hi); __half* wkh  = (__half*)p;
    cudaGetSymbolAddress(&p, g_wk_lo); __half* wkl  = (__half*)p;
    cudaGetSymbolAddress(&p, g_wv_hi); __half* wvh  = (__half*)p;
    cudaGetSymbolAddress(&p, g_wv_lo); __half* wvl  = (__half*)p;
    cudaGetSymbolAddress(&p, g_wp_hi); __half* wph  = (__half*)p;
    cudaGetSymbolAddress(&p, g_wp_lo); __half* wpl  = (__half*)p;
    cudaGetSymbolAddress(&p, g_b2d_q); float*  b2q  = (float*)p;
    cudaGetSymbolAddress(&p, g_b2d_k); float*  b2k  = (float*)p;
    cudaGetSymbolAddress(&p, g_b2d_v); float*  b2v  = (float*)p;
    cudaGetSymbolAddress(&p, g_b2d_p); float*  b2p  = (float*)p;

    const int perT1 = Bd * Cd  * Nd;   //  4,194,304
    const int perTv = Bd * CVd * Nd;   // 16,777,216

    // 0. weight folding + split, bias broadcast tables
    prep_w<<<(Cd  * Cd  + 255) / 256, 256>>>(wq, q_scale, wqh, wql, Cd,  Cd);
    prep_w<<<(Cd  * Cd  + 255) / 256, 256>>>(wk, k_scale, wkh, wkl, Cd,  Cd);
    prep_w<<<(CVd * Cd  + 255) / 256, 256>>>(wv, v_scale, wvh, wvl, CVd, Cd);
    prep_w<<<(Cd  * CVd + 255) / 256, 256>>>(wp, p_scale, wph, wpl, Cd,  CVd);
    prep_b<<<(Cd  * 128 + 255) / 256, 256>>>(q_bias, b2q, Cd);
    prep_b<<<(Cd  * 128 + 255) / 256, 256>>>(k_bias, b2k, Cd);
    prep_b<<<(CVd * 128 + 255) / 256, 256>>>(v_bias, b2v, CVd);
    prep_b<<<(Cd  * 128 + 255) / 256, 256>>>(p_bias, b2p, Cd);

    // 1. head spikes (fp16)
    sfa_f2h<<<perT1 / 256, 256>>>(x, xs, perT1);

    // 2. q/k/v conv + BN (tensor cores, split weights, bias in acc init)
    conv_wmma<<<dim3(2,  4, TBd), 256>>>(wqh, wql, xs, b2q, qf, Cd,  Cd);
    conv_wmma<<<dim3(2,  4, TBd), 256>>>(wkh, wkl, xs, b2k, kf, Cd,  Cd);
    conv_wmma<<<dim3(2, 16, TBd), 256>>>(wvh, wvl, xs, b2v, vf, CVd, Cd);

    // 3. spike q/k/v (fp16)
    sfa_f2h<<<perT1 / 256, 256>>>(qf, qh, perT1);
    sfa_f2h<<<perT1 / 256, 256>>>(kf, kh, perT1);
    sfa_f2h<<<perTv / 256, 256>>>(vf, vh, perTv);

    // 4. linear attention (exact in fp16/fp32): O = 0.25 * Q^T (K V^T)
    kv_wmma<<<Zd, 256>>>();
    kv_split<<<(Zd * DHd * DVd + 255) / 256, 256>>>(Zd * DHd * DVd);
    av_wmma<<<dim3(2, 2, Zd), 256>>>();

    // 5. attn spikes (fp16)
    sfa_f2h<<<perTv / 256, 256>>>(of, oh, perTv);

    // 6. projection conv + BN -> output (fp32)
    conv_wmma<<<dim3(2, 4, TBd), 256>>>(wph, wpl, oh, b2p, out, Cd, CVd);
}